// round 6
// baseline (speedup 1.0000x reference)
#include <cuda_runtime.h>
#include <cuda_fp16.h>
#include <cstdint>

#define NF  16384   // n_features
#define ND  768     // d_model
#define NBS 1024    // B*S
#define NM  262144  // n_connections

// Scratch (device globals — no cudaMalloc allowed)
__device__ __align__(16) __half g_decH[(size_t)NF * ND];   // up_decoder transposed [F, D] fp16
__device__ __align__(16) __half g_upH [(size_t)NF * NBS];  // up_facts transposed  [F, BS] fp16
__device__ __align__(16) float  g_vals[NM];
__device__ int g_seg[NF + 1];

// ---------------------------------------------------------------------------
// 32x32 tiled transpose fp32 -> fp16
// ---------------------------------------------------------------------------
__global__ void transpose32_h(const float* __restrict__ in, __half* __restrict__ out,
                              int rows, int cols) {
    __shared__ float tile[32][33];
    int c0 = blockIdx.x * 32;
    int r0 = blockIdx.y * 32;
    int x = threadIdx.x, y = threadIdx.y;
#pragma unroll
    for (int k = 0; k < 32; k += 8)
        tile[y + k][x] = in[(size_t)(r0 + y + k) * cols + (c0 + x)];
    __syncthreads();
#pragma unroll
    for (int k = 0; k < 32; k += 8)
        out[(size_t)(c0 + y + k) * rows + (r0 + x)] = __float2half_rn(tile[x][y + k]);
}

// ---------------------------------------------------------------------------
// Segment boundaries: g_seg[f] = first m with i_indices[m] >= f (i sorted).
// ---------------------------------------------------------------------------
__global__ void segstart_kernel(const int* __restrict__ iidx) {
    int f = blockIdx.x * blockDim.x + threadIdx.x;
    if (f > NF) return;
    int lo = 0, hi = NM;
    while (lo < hi) {
        int mid = (lo + hi) >> 1;
        if (iidx[mid] < f) lo = mid + 1; else hi = mid;
    }
    g_seg[f] = lo;
}

// ---------------------------------------------------------------------------
// values v3: warp per 4 consecutive connections; Enc row (fp32) cached in
// registers across equal sorted i. Dec rows are fp16 (half the L2 bytes).
// Element mapping: lane owns elements {256k + 8*lane + c : k=0..2, c=0..7}.
//   dec: float4 chunk (8 halves) at index lane + 32k
//   enc: float4 pairs at indices 2*lane + 64k and 2*lane+1 + 64k
// ---------------------------------------------------------------------------
#define VG 4
__device__ __forceinline__ float dot8(float4 a_lo, float4 a_hi, float4 hraw, float s) {
    const __half2* h = (const __half2*)&hraw;
    float2 u0 = __half22float2(h[0]);
    float2 u1 = __half22float2(h[1]);
    float2 u2 = __half22float2(h[2]);
    float2 u3 = __half22float2(h[3]);
    s += a_lo.x * u0.x + a_lo.y * u0.y + a_lo.z * u1.x + a_lo.w * u1.y;
    s += a_hi.x * u2.x + a_hi.y * u2.y + a_hi.z * u3.x + a_hi.w * u3.y;
    return s;
}

__global__ void values_kernel(const float* __restrict__ enc,
                              const int* __restrict__ iidx,
                              const int* __restrict__ jidx) {
    int warp = (blockIdx.x * blockDim.x + threadIdx.x) >> 5;
    int lane = threadIdx.x & 31;
    int m0 = warp * VG;
    if (m0 >= NM) return;

    float4 a0, a1, a2, a3, a4, a5;
    int prev_i = -1;

#pragma unroll
    for (int g = 0; g < VG; g++) {
        int m = m0 + g;
        int i = iidx[m];
        int j = jidx[m];
        if (i != prev_i) {
            const float4* ap = (const float4*)(enc + (size_t)i * ND);
            a0 = ap[2 * lane];       a1 = ap[2 * lane + 1];
            a2 = ap[2 * lane + 64];  a3 = ap[2 * lane + 65];
            a4 = ap[2 * lane + 128]; a5 = ap[2 * lane + 129];
            prev_i = i;
        }
        const float4* bp = (const float4*)(g_decH + (size_t)j * ND);  // 96 float4 of halves
        float4 q0 = bp[lane];
        float4 q1 = bp[lane + 32];
        float4 q2 = bp[lane + 64];

        float s = 0.f;
        s = dot8(a0, a1, q0, s);
        s = dot8(a2, a3, q1, s);
        s = dot8(a4, a5, q2, s);

#pragma unroll
        for (int off = 16; off; off >>= 1)
            s += __shfl_xor_sync(0xFFFFFFFFu, s, off);
        if (lane == 0) g_vals[m] = s;
    }
}

// ---------------------------------------------------------------------------
// Fused scatter + output transpose.
// CTA = (32 features) x (256 bs columns), 128 threads (thread t owns half2
// columns 2t, 2t+1). Features processed sequentially -> scalar fp32 acc pair.
// Result staged in padded smem tile, then written directly to out[bs, f]
// (128B-coalesced rows), eliminating the outT buffer + final transpose.
// ---------------------------------------------------------------------------
#define TF  32
#define TBS 256
__global__ void __launch_bounds__(128) scatter_kernel(const int* __restrict__ jidx,
                                                      float* __restrict__ out) {
    __shared__ float tile[TF][TBS + 1];   // stride 257 floats -> conflict-free reads
    int f0  = blockIdx.x * TF;
    int bs0 = blockIdx.y * TBS;
    int t   = threadIdx.x;                // 0..127

    for (int lf = 0; lf < TF; lf++) {
        int s0 = g_seg[f0 + lf], s1 = g_seg[f0 + lf + 1];
        float ax = 0.f, ay = 0.f;
        #pragma unroll 2
        for (int m = s0; m < s1; m++) {
            float v = g_vals[m];          // broadcast
            int   j = jidx[m];            // broadcast
            __half2 h = *((const __half2*)(g_upH + (size_t)j * NBS + bs0) + t);
            float2 u = __half22float2(h);
            ax += v * u.x;
            ay += v * u.y;
        }
        tile[lf][2 * t]     = ax;
        tile[lf][2 * t + 1] = ay;
    }
    __syncthreads();

    // Write 32x256 tile to out[bs0+r][f0+c]; consecutive lanes -> consecutive c
    // = 128B contiguous stores. tile read tile[c][r] stride-257 -> no conflicts.
    for (int idx = t; idx < TF * TBS; idx += 128) {
        int c = idx & (TF - 1);
        int r = idx >> 5;
        out[(size_t)(bs0 + r) * NF + f0 + c] = tile[c][r];
    }
}

// ---------------------------------------------------------------------------
extern "C" void kernel_launch(void* const* d_in, const int* in_sizes, int n_in,
                              void* d_out, int out_size) {
    const float* up_facts = (const float*)d_in[0];  // [BS, F]
    const float* enc      = (const float*)d_in[1];  // [F, D]  down_encoder
    const float* dec      = (const float*)d_in[2];  // [D, F]  up_decoder
    const int*   iidx     = (const int*)d_in[3];    // [M] int32, sorted
    const int*   jidx     = (const int*)d_in[4];    // [M] int32
    float*       out      = (float*)d_out;          // [BS, F]

    __half* decH = nullptr; __half* upH = nullptr;
    cudaGetSymbolAddress((void**)&decH, g_decH);
    cudaGetSymbolAddress((void**)&upH,  g_upH);

    dim3 tb(32, 8);

    // 1. Dec [D,F] -> decH [F,D] fp16
    transpose32_h<<<dim3(NF / 32, ND / 32), tb>>>(dec, decH, ND, NF);
    // 2. up_facts [BS,F] -> upH [F,BS] fp16
    transpose32_h<<<dim3(NF / 32, NBS / 32), tb>>>(up_facts, upH, NBS, NF);
    // 3. segment starts
    segstart_kernel<<<(NF + 1 + 255) / 256, 256>>>(iidx);
    // 4. per-connection dot products
    values_kernel<<<(NM / VG) * 32 / 256, 256>>>(enc, iidx, jidx);
    // 5. fused segment reduction + transpose into out
    scatter_kernel<<<dim3(NF / TF, NBS / TBS), 128>>>(jidx, out);
}

// round 7
// speedup vs baseline: 2.0002x; 2.0002x over previous
#include <cuda_runtime.h>
#include <cuda_fp16.h>
#include <cstdint>

#define NF  16384   // n_features
#define ND  768     // d_model
#define NBS 1024    // B*S
#define NM  262144  // n_connections

// Scratch (device globals — no cudaMalloc allowed)
__device__ __align__(16) __half g_decH[(size_t)NF * ND];   // up_decoder transposed [F, D] fp16
__device__ __align__(16) __half g_upH [(size_t)NF * NBS];  // up_facts transposed  [F, BS] fp16
__device__ __align__(16) float  g_vals[NM];
__device__ int g_seg[NF + 1];

// ---------------------------------------------------------------------------
// 32x32 tiled transpose fp32 -> fp16
// ---------------------------------------------------------------------------
__global__ void transpose32_h(const float* __restrict__ in, __half* __restrict__ out,
                              int rows, int cols) {
    __shared__ float tile[32][33];
    int c0 = blockIdx.x * 32;
    int r0 = blockIdx.y * 32;
    int x = threadIdx.x, y = threadIdx.y;
#pragma unroll
    for (int k = 0; k < 32; k += 8)
        tile[y + k][x] = in[(size_t)(r0 + y + k) * cols + (c0 + x)];
    __syncthreads();
#pragma unroll
    for (int k = 0; k < 32; k += 8)
        out[(size_t)(c0 + y + k) * rows + (r0 + x)] = __float2half_rn(tile[x][y + k]);
}

// ---------------------------------------------------------------------------
// Segment boundaries: g_seg[f] = first m with i_indices[m] >= f (i sorted).
// ---------------------------------------------------------------------------
__global__ void segstart_kernel(const int* __restrict__ iidx) {
    int f = blockIdx.x * blockDim.x + threadIdx.x;
    if (f > NF) return;
    int lo = 0, hi = NM;
    while (lo < hi) {
        int mid = (lo + hi) >> 1;
        if (iidx[mid] < f) lo = mid + 1; else hi = mid;
    }
    g_seg[f] = lo;
}

// ---------------------------------------------------------------------------
// values v3 (unchanged from R6, measured 52us): warp per 4 consecutive
// connections; fp32 Enc row cached in registers across equal sorted i;
// fp16 Dec rows.
// ---------------------------------------------------------------------------
#define VG 4
__device__ __forceinline__ float dot8(float4 a_lo, float4 a_hi, float4 hraw, float s) {
    const __half2* h = (const __half2*)&hraw;
    float2 u0 = __half22float2(h[0]);
    float2 u1 = __half22float2(h[1]);
    float2 u2 = __half22float2(h[2]);
    float2 u3 = __half22float2(h[3]);
    s += a_lo.x * u0.x + a_lo.y * u0.y + a_lo.z * u1.x + a_lo.w * u1.y;
    s += a_hi.x * u2.x + a_hi.y * u2.y + a_hi.z * u3.x + a_hi.w * u3.y;
    return s;
}

__global__ void values_kernel(const float* __restrict__ enc,
                              const int* __restrict__ iidx,
                              const int* __restrict__ jidx) {
    int warp = (blockIdx.x * blockDim.x + threadIdx.x) >> 5;
    int lane = threadIdx.x & 31;
    int m0 = warp * VG;
    if (m0 >= NM) return;

    float4 a0, a1, a2, a3, a4, a5;
    int prev_i = -1;

#pragma unroll
    for (int g = 0; g < VG; g++) {
        int m = m0 + g;
        int i = iidx[m];
        int j = jidx[m];
        if (i != prev_i) {
            const float4* ap = (const float4*)(enc + (size_t)i * ND);
            a0 = ap[2 * lane];       a1 = ap[2 * lane + 1];
            a2 = ap[2 * lane + 64];  a3 = ap[2 * lane + 65];
            a4 = ap[2 * lane + 128]; a5 = ap[2 * lane + 129];
            prev_i = i;
        }
        const float4* bp = (const float4*)(g_decH + (size_t)j * ND);
        float4 q0 = bp[lane];
        float4 q1 = bp[lane + 32];
        float4 q2 = bp[lane + 64];

        float s = 0.f;
        s = dot8(a0, a1, q0, s);
        s = dot8(a2, a3, q1, s);
        s = dot8(a4, a5, q2, s);

#pragma unroll
        for (int off = 16; off; off >>= 1)
            s += __shfl_xor_sync(0xFFFFFFFFu, s, off);
        if (lane == 0) g_vals[m] = s;
    }
}

// ---------------------------------------------------------------------------
// Scatter v4: fused segment-reduce + output transpose, R4 latency structure.
// CTA = TF=8 features x full 1024 bs. 256 threads; thread t owns columns
// 4t..4t+3 (one float2-of-half2 = 8B load -> full 2KB row wavefront per
// connection). The CTA's whole (j,v) range is staged in smem ONCE (2
// barriers), then per-feature inner loops run entirely from smem + L2 row
// loads (independent iterations -> deep MLP). Fallback chunking if a CTA's
// range exceeds SSTG (never at avg 128, but correctness-safe).
// Output staged in 8x1025 smem tile, written coalesced in final layout.
// ---------------------------------------------------------------------------
#define TF   8
#define SSTG 512
__global__ void __launch_bounds__(256) scatter_kernel(const int* __restrict__ jidx,
                                                      float* __restrict__ out) {
    __shared__ float tile[TF][NBS + 1];    // 8 x 1025 floats = 32.8 KB
    __shared__ int   sj[SSTG];
    __shared__ float sv[SSTG];
    __shared__ int   sseg[TF + 1];

    int f0 = blockIdx.x * TF;
    int t  = threadIdx.x;                  // 0..255

    if (t <= TF) sseg[t] = g_seg[f0 + t];
    __syncthreads();
    int mbase = sseg[0];
    int mend  = sseg[TF];
    int total = mend - mbase;

    const float2* up2 = (const float2*)g_upH;   // [F][BS/4] float2 (4 halves)

    if (total <= SSTG) {
        // ---- fast path: stage everything once ----
        for (int k = t; k < total; k += 256) {
            sj[k] = jidx[mbase + k];
            sv[k] = g_vals[mbase + k];
        }
        __syncthreads();
#pragma unroll
        for (int lf = 0; lf < TF; lf++) {
            int s0 = sseg[lf] - mbase, s1 = sseg[lf + 1] - mbase;
            float ax = 0.f, ay = 0.f, az = 0.f, aw = 0.f;
            for (int k = s0; k < s1; k++) {
                float v = sv[k];
                float2 raw = up2[(size_t)sj[k] * (NBS / 4) + t];
                float2 u0 = __half22float2(*(__half2*)&raw.x);
                float2 u1 = __half22float2(*(__half2*)&raw.y);
                ax += v * u0.x; ay += v * u0.y;
                az += v * u1.x; aw += v * u1.y;
            }
            tile[lf][4 * t]     = ax;
            tile[lf][4 * t + 1] = ay;
            tile[lf][4 * t + 2] = az;
            tile[lf][4 * t + 3] = aw;
        }
    } else {
        // ---- fallback: per-feature chunking (rare) ----
        for (int lf = 0; lf < TF; lf++) {
            int s0 = sseg[lf], s1 = sseg[lf + 1];
            float ax = 0.f, ay = 0.f, az = 0.f, aw = 0.f;
            for (int base = s0; base < s1; base += SSTG) {
                int len = min(SSTG, s1 - base);
                __syncthreads();
                for (int k = t; k < len; k += 256) {
                    sj[k] = jidx[base + k];
                    sv[k] = g_vals[base + k];
                }
                __syncthreads();
                for (int k = 0; k < len; k++) {
                    float v = sv[k];
                    float2 raw = up2[(size_t)sj[k] * (NBS / 4) + t];
                    float2 u0 = __half22float2(*(__half2*)&raw.x);
                    float2 u1 = __half22float2(*(__half2*)&raw.y);
                    ax += v * u0.x; ay += v * u0.y;
                    az += v * u1.x; aw += v * u1.y;
                }
            }
            tile[lf][4 * t]     = ax;
            tile[lf][4 * t + 1] = ay;
            tile[lf][4 * t + 2] = az;
            tile[lf][4 * t + 3] = aw;
        }
    }
    __syncthreads();

    // Write 8 x 1024 tile to out[r][f0 + c]: warp covers 4 rows x 8 cols
    // = 4 contiguous 32B segments per warp; fully coalesced across warps.
    for (int idx = t; idx < TF * NBS; idx += 256) {
        int c = idx & (TF - 1);
        int r = idx >> 3;
        out[(size_t)r * NF + f0 + c] = tile[c][r];
    }
}

// ---------------------------------------------------------------------------
extern "C" void kernel_launch(void* const* d_in, const int* in_sizes, int n_in,
                              void* d_out, int out_size) {
    const float* up_facts = (const float*)d_in[0];  // [BS, F]
    const float* enc      = (const float*)d_in[1];  // [F, D]  down_encoder
    const float* dec      = (const float*)d_in[2];  // [D, F]  up_decoder
    const int*   iidx     = (const int*)d_in[3];    // [M] int32, sorted
    const int*   jidx     = (const int*)d_in[4];    // [M] int32
    float*       out      = (float*)d_out;          // [BS, F]

    __half* decH = nullptr; __half* upH = nullptr;
    cudaGetSymbolAddress((void**)&decH, g_decH);
    cudaGetSymbolAddress((void**)&upH,  g_upH);

    dim3 tb(32, 8);

    // 1. Dec [D,F] -> decH [F,D] fp16
    transpose32_h<<<dim3(NF / 32, ND / 32), tb>>>(dec, decH, ND, NF);
    // 2. up_facts [BS,F] -> upH [F,BS] fp16
    transpose32_h<<<dim3(NF / 32, NBS / 32), tb>>>(up_facts, upH, NBS, NF);
    // 3. segment starts
    segstart_kernel<<<(NF + 1 + 255) / 256, 256>>>(iidx);
    // 4. per-connection dot products
    values_kernel<<<(NM / VG) * 32 / 256, 256>>>(enc, iidx, jidx);
    // 5. fused segment reduction + transpose into out
    scatter_kernel<<<NF / TF, 256>>>(jidx, out);
}